// round 14
// baseline (speedup 1.0000x reference)
#include <cuda_runtime.h>
#include <cuda_fp16.h>
#include <math.h>
#include <stdint.h>

#define DIMC   1024
#define NB     2
#define NSEQ   2048
#define NHEADS 16
#define NEFF   8
#define HDIM   64
#define HD2    128
#define MTOT   (NB*NSEQ)          // 4096
#define L2E    1.4426950408889634f

// ---------------- scratch (device globals; no allocations allowed) ----------
__device__ float  g_lambda;
__device__ __half g_xh[MTOT*DIMC];              // fp16 x
__device__ __half g_wh[4][DIMC*DIMC];           // fp16 Wq,Wk,Wv,Wo
__device__ __half g_qh[NB*NHEADS*NSEQ*HDIM];    // [b,h,n,hd] pre-scaled fp16
__device__ __half g_kh[NB*NHEADS*NSEQ*HDIM];    // [b,h,n,hd] fp16
__device__ __half g_vh[NB*NEFF*NSEQ*HD2];       // [b,e,n,128] fp16 natural
__device__ __half g_vt[NB*NEFF*HD2*NSEQ];       // [b,e,d,n]  fp16 transposed
__device__ __half g_combh[MTOT*DIMC];           // combined+normed fp16

// ==================== helpers ======================
__device__ __forceinline__ uint32_t smem_u32(const void* p) {
    uint32_t a;
    asm("{ .reg .u64 t; cvta.to.shared.u64 t, %1; cvt.u32.u64 %0, t; }" : "=r"(a) : "l"(p));
    return a;
}
__device__ __forceinline__ uint32_t packh2(float a, float b) {
    __half2 h = __floats2half2_rn(a, b);
    return *(uint32_t*)&h;
}

// m16n8k16 fp16 mma, fp32 accum: D += A(row) * B(col)
__device__ __forceinline__ void mma16(float* d, const uint32_t* a, uint32_t b0, uint32_t b1) {
    asm volatile("mma.sync.aligned.m16n8k16.row.col.f32.f16.f16.f32 "
                 "{%0,%1,%2,%3}, {%4,%5,%6,%7}, {%8,%9}, {%0,%1,%2,%3};"
                 : "+f"(d[0]), "+f"(d[1]), "+f"(d[2]), "+f"(d[3])
                 : "r"(a[0]), "r"(a[1]), "r"(a[2]), "r"(a[3]), "r"(b0), "r"(b1));
}

#define LDSM4(r0, r1, r2, r3, addr) \
    asm volatile("ldmatrix.sync.aligned.m8n8.x4.shared.b16 {%0,%1,%2,%3}, [%4];" \
                 : "=r"(r0), "=r"(r1), "=r"(r2), "=r"(r3) : "r"(addr))

#define CP_ASYNC16(dst, src) \
    asm volatile("cp.async.cg.shared.global [%0], [%1], 16;" :: "r"(dst), "l"(src) : "memory")
#define CP_COMMIT() asm volatile("cp.async.commit_group;" ::: "memory")
#define CP_WAIT1()  asm volatile("cp.async.wait_group 1;" ::: "memory")
#define CP_WAIT2()  asm volatile("cp.async.wait_group 2;" ::: "memory")

// ---------------- fp16 pre-round ------------------------
__global__ __launch_bounds__(256) void round_kernel(const float* __restrict__ src,
                                                    __half* __restrict__ dst)
{
    int i = (blockIdx.x * 256 + threadIdx.x) * 4;
    float4 v = *(const float4*)(src + i);
    uint2 o;
    o.x = packh2(v.x, v.y);
    o.y = packh2(v.z, v.w);
    *(uint2*)(dst + i) = o;
}

// fused: all four weight matrices in one launch (1024 blocks each)
__global__ __launch_bounds__(256) void round4_kernel(const float* __restrict__ s0,
                                                     const float* __restrict__ s1,
                                                     const float* __restrict__ s2,
                                                     const float* __restrict__ s3)
{
    int wsel = blockIdx.x >> 10;
    const float* src = (wsel == 0) ? s0 : (wsel == 1) ? s1 : (wsel == 2) ? s2 : s3;
    int i = ((blockIdx.x & 1023) * 256 + threadIdx.x) * 4;
    float4 v = *(const float4*)(src + i);
    uint2 o;
    o.x = packh2(v.x, v.y);
    o.y = packh2(v.z, v.w);
    *(uint2*)(&g_wh[wsel][0] + i) = o;
}

// ---------------- lambda = exp(lq1.lk1) - exp(lq2.lk2) + 0.8 ----------------
__global__ void lambda_kernel(const float* __restrict__ lq1, const float* __restrict__ lk1,
                              const float* __restrict__ lq2, const float* __restrict__ lk2)
{
    int t = threadIdx.x;
    float s1 = 0.f, s2 = 0.f;
    for (int i = t; i < HDIM; i += 32) {
        s1 += lq1[i] * lk1[i];
        s2 += lq2[i] * lk2[i];
    }
    #pragma unroll
    for (int off = 16; off > 0; off >>= 1) {
        s1 += __shfl_xor_sync(0xffffffffu, s1, off);
        s2 += __shfl_xor_sync(0xffffffffu, s2, off);
    }
    if (t == 0) g_lambda = expf(s1) - expf(s2) + 0.8f;
}

// ---------------- V transpose: g_vh [be][n][128] -> g_vt [be][d][2048] ------
__global__ __launch_bounds__(256) void vtrans_kernel()
{
    __shared__ __half T[64][136];
    int be = blockIdx.y;
    int n0 = blockIdx.x * 64;
    const __half* src = g_vh + ((size_t)be * NSEQ + n0) * HD2;
    int tid = threadIdx.x;
    #pragma unroll
    for (int i = 0; i < 4; i++) {
        int id = tid + i * 256;
        int r = id >> 4, c8 = (id & 15) * 8;
        *(uint4*)&T[r][c8] = *(const uint4*)(src + (size_t)r * HD2 + c8);
    }
    __syncthreads();
    __half* dst = g_vt + (size_t)be * HD2 * NSEQ;
    #pragma unroll
    for (int i = 0; i < 16; i++) {
        int id = tid + i * 256;
        int d = id >> 5, h2 = id & 31;
        __half2 v = __halves2half2(T[2 * h2][d], T[2 * h2 + 1][d]);
        *(__half2*)(dst + (size_t)d * NSEQ + n0 + 2 * h2) = v;
    }
}

// ============ fp16 mma.sync GEMM NT, 4-stage cp.async, ldmatrix =============
// 256 threads (8 warps), CTA 128x128, warp 32x64, K-chunk 32.
#define SSH (128*40)       // halfs per matrix per stage (row stride 40)

__global__ __launch_bounds__(256, 2) void gemm_mma_kernel(const __half* __restrict__ A,
                                                          const __half* __restrict__ Wp,
                                                          const float* __restrict__ b0,
                                                          const float* __restrict__ b1,
                                                          const float* __restrict__ b2,
                                                          float* __restrict__ outp, int fused)
{
    extern __shared__ __half smh[];
    uint32_t sbase = smem_u32(smh);

    int mode = fused ? (int)blockIdx.z : 3;
    const __half* W = fused ? &g_wh[mode][0] : Wp;
    const float* bias = (mode == 1) ? b1 : (mode == 2) ? b2 : b0;
    const __half* Ap = (mode == 3) ? g_combh : A;

    int m0 = blockIdx.y * 128;
    int n0 = blockIdx.x * 128;
    int tid = threadIdx.x, wid = tid >> 5, lane = tid & 31;
    int wm = wid >> 1, wn = wid & 1;
    int g = lane >> 2, tg = lane & 3;
    int lm = lane >> 3, lr = lane & 7;
    int a_r = (lm & 1) * 8 + lr, a_c = (lm >> 1) * 8;
    int b_r = (lm >> 1) * 8 + lr, b_c = (lm & 1) * 8;

    int lrow = tid >> 2;                  // 0..63 (row step 64)
    int lc16 = tid & 3;                   // 16B-chunk within row

    float acc[2][8][4];
    #pragma unroll
    for (int mi = 0; mi < 2; mi++)
        #pragma unroll
        for (int ni = 0; ni < 8; ni++)
            #pragma unroll
            for (int j = 0; j < 4; j++) acc[mi][ni][j] = 0.f;

    #define GEMM_ISSUE(c, st) do { \
        uint32_t as = sbase + (uint32_t)((st) * 2 * SSH) * 2u; \
        uint32_t bs = as + (uint32_t)SSH * 2u; \
        const __half* ag = Ap + (size_t)m0 * DIMC + (c) * 32; \
        const __half* bg = W  + (size_t)n0 * DIMC + (c) * 32; \
        _Pragma("unroll") \
        for (int i = 0; i < 2; i++) { \
            int row = lrow + i * 64; \
            CP_ASYNC16(as + (uint32_t)(row * 40 + lc16 * 8) * 2u, ag + (size_t)row * DIMC + lc16 * 8); \
            CP_ASYNC16(bs + (uint32_t)(row * 40 + lc16 * 8) * 2u, bg + (size_t)row * DIMC + lc16 * 8); \
        } \
    } while (0)

    GEMM_ISSUE(0, 0); CP_COMMIT();
    GEMM_ISSUE(1, 1); CP_COMMIT();
    GEMM_ISSUE(2, 2); CP_COMMIT();

    uint32_t a_base = (uint32_t)((wm * 32 + a_r) * 40 + a_c) * 2u;
    uint32_t b_base = (uint32_t)((wn * 64 + b_r) * 40 + b_c) * 2u + (uint32_t)SSH * 2u;

    for (int c = 0; c < 32; c++) {
        int st = c & 3;
        CP_WAIT2();
        __syncthreads();
        if (c + 3 < 32) GEMM_ISSUE(c + 3, (c + 3) & 3);
        CP_COMMIT();

        uint32_t stb = sbase + (uint32_t)(st * 2 * SSH) * 2u;
        #pragma unroll
        for (int kk = 0; kk < 2; kk++) {
            uint32_t a0[4], a1[4];
            LDSM4(a0[0], a0[1], a0[2], a0[3], stb + a_base + (uint32_t)(kk * 16) * 2u);
            LDSM4(a1[0], a1[1], a1[2], a1[3], stb + a_base + (uint32_t)(16 * 40 + kk * 16) * 2u);
            #pragma unroll
            for (int p = 0; p < 4; p++) {
                uint32_t b0r, b1r, b2r, b3r;
                LDSM4(b0r, b1r, b2r, b3r, stb + b_base + (uint32_t)(p * 16 * 40 + kk * 16) * 2u);
                mma16(acc[0][2*p],   a0, b0r, b1r);
                mma16(acc[0][2*p+1], a0, b2r, b3r);
                mma16(acc[1][2*p],   a1, b0r, b1r);
                mma16(acc[1][2*p+1], a1, b2r, b3r);
            }
        }
    }
    #undef GEMM_ISSUE

    // epilogue: scatter with bias
    #pragma unroll
    for (int mi = 0; mi < 2; mi++) {
        int m = m0 + wm * 32 + mi * 16 + g;
        #pragma unroll
        for (int ni = 0; ni < 8; ni++) {
            int n = n0 + wn * 64 + ni * 8 + tg * 2;
            float2 bs2 = *(const float2*)(bias + n);
            #pragma unroll
            for (int half_ = 0; half_ < 2; half_++) {
                int mm = m + half_ * 8;
                float x = acc[mi][ni][half_ * 2 + 0] + bs2.x;
                float y = acc[mi][ni][half_ * 2 + 1] + bs2.y;
                int b_ = mm >> 11, nn = mm & 2047;
                if (mode == 0) {
                    int h = n >> 6, hd = n & 63;
                    *(uint32_t*)(g_qh + (((size_t)(b_*NHEADS+h))*NSEQ+nn)*HDIM + hd) =
                        packh2(x * 0.125f, y * 0.125f);
                } else if (mode == 1) {
                    int h = n >> 6, hd = n & 63;
                    *(uint32_t*)(g_kh + (((size_t)(b_*NHEADS+h))*NSEQ+nn)*HDIM + hd) =
                        packh2(x, y);
                } else if (mode == 2) {
                    int e = n >> 7, d2 = n & 127;
                    *(uint32_t*)(g_vh + (((size_t)(b_*NEFF+e))*NSEQ+nn)*HD2 + d2) =
                        packh2(x, y);
                } else {
                    *(float2*)(outp + (size_t)mm * DIMC + n) = make_float2(x, y);
                }
            }
        }
    }
}

// ---------------- paired-head flash attention, 64 q-rows, 2 CTAs/SM ---------
// 256 threads = 8 warps; warps 0-3 head 2e, warps 4-7 head 2e+1; shared V.
// Epilogue: diff, RMSNorm, write g_combh fp16 (no g_attn round-trip).
__global__ __launch_bounds__(256, 2) void flash_kernel(const float* __restrict__ norm_w)
{
    extern __shared__ __half sh[];
    __half* Qs = sh;                    // [2 head][64][72]
    __half* Ks = Qs + 2 * 64 * 72;      // [2 buf][2 head][64][72]
    __half* Vs = Ks + 2 * 2 * 64 * 72;  // [2 buf][128][72]  transposed [d][key]
    float*  Os = (float*)Ks;            // epilogue overlay [64][132] f32

    int qt = blockIdx.x;                // 0..31  (64-row q tiles)
    int be = blockIdx.y;                // 0..15
    int b_ = be >> 3, e = be & 7;
    int bh0 = b_ * NHEADS + 2 * e;

    const __half* Qg = g_qh + ((size_t)bh0 * NSEQ + qt * 64) * HDIM;
    const __half* Kg = g_kh + (size_t)bh0 * NSEQ * HDIM;   // two heads contiguous
    const __half* Vg = g_vt + ((size_t)(b_ * NEFF + e)) * HD2 * NSEQ;  // [d][n]

    int tid = threadIdx.x, wid = tid >> 5, lane = tid & 31;
    int hs = wid >> 2, w4 = wid & 3;
    int g = lane >> 2, tg = lane & 3;
    int lm = lane >> 3, lr = lane & 7;
    int a_r = (lm & 1) * 8 + lr, a_c = (lm >> 1) * 8;
    int b_r = (lm >> 1) * 8 + lr, b_c = (lm & 1) * 8;
    uint32_t qbase = smem_u32(Qs);
    uint32_t kbase = smem_u32(Ks);
    uint32_t vbase = smem_u32(Vs);

    // ---- prologue: Q both heads (group 0)
    #pragma unroll
    for (int i = 0; i < 4; i++) {
        int id = tid + i * 256;
        int head = id >> 9, rem = id & 511;
        int row = rem >> 3, c8 = (rem & 7) * 8;
        CP_ASYNC16(qbase + (uint32_t)((head * 64 + row) * 72 + c8) * 2u,
                   Qg + (size_t)head * NSEQ * HDIM + (size_t)row * HDIM + c8);
    }
    CP_COMMIT();
    // K0 both heads + V0 (group 1)
    #pragma unroll
    for (int i = 0; i < 4; i++) {
        int id = tid + i * 256;
        int head = id >> 9, rem = id & 511;
        int key = rem >> 3, c8 = (rem & 7) * 8;
        CP_ASYNC16(kbase + (uint32_t)((head * 64 + key) * 72 + c8) * 2u,
                   Kg + (size_t)head * NSEQ * HDIM + (size_t)key * HDIM + c8);
    }
    #pragma unroll
    for (int i = 0; i < 4; i++) {
        int id = tid + i * 256;
        int row = id >> 3, c8 = (id & 7) * 8;       // row = d
        CP_ASYNC16(vbase + (uint32_t)(row * 72 + c8) * 2u, Vg + (size_t)row * NSEQ + c8);
    }
    CP_COMMIT();
    CP_WAIT1();            // Q group done
    __syncthreads();

    // hoist Q fragments (kt-invariant)
    uint32_t qf[4][4];
    uint32_t q_off = qbase + (uint32_t)((hs * 64 + w4 * 16 + a_r) * 72 + a_c) * 2u;
    #pragma unroll
    for (int kk = 0; kk < 4; kk++)
        LDSM4(qf[kk][0], qf[kk][1], qf[kk][2], qf[kk][3], q_off + (uint32_t)(kk * 16) * 2u);

    uint32_t kf_off = (uint32_t)(b_r * 72 + b_c) * 2u;

    float o[16][4];
    #pragma unroll
    for (int ni = 0; ni < 16; ni++)
        #pragma unroll
        for (int j = 0; j < 4; j++) o[ni][j] = 0.f;
    float mrun[2] = {-1e30f, -1e30f};
    float lrun[2] = {0.f, 0.f};

    for (int kt = 0; kt < 32; kt++) {
        int buf = kt & 1;
        if (kt + 1 < 32) {
            uint32_t kb = kbase + (uint32_t)((buf ^ 1) * 2 * 64 * 72) * 2u;
            uint32_t vb = vbase + (uint32_t)((buf ^ 1) * 128 * 72) * 2u;
            #pragma unroll
            for (int i = 0; i < 4; i++) {
                int id = tid + i * 256;
                int head = id >> 9, rem = id & 511;
                int key = rem >> 3, c8 = (rem & 7) * 8;
                CP_ASYNC16(kb + (uint32_t)((head * 64 + key) * 72 + c8) * 2u,
                           Kg + (size_t)head * NSEQ * HDIM +
                               (size_t)((kt + 1) * 64 + key) * HDIM + c8);
            }
            #pragma unroll
            for (int i = 0; i < 4; i++) {
                int id = tid + i * 256;
                int row = id >> 3, c8 = (id & 7) * 8;
                CP_ASYNC16(vb + (uint32_t)(row * 72 + c8) * 2u,
                           Vg + (size_t)row * NSEQ + (kt + 1) * 64 + c8);
            }
        }
        CP_COMMIT();
        CP_WAIT1();
        __syncthreads();

        // ---- S = Q K^T (own head's K region)
        uint32_t Kb = kbase + (uint32_t)((buf * 2 + hs) * 64 * 72) * 2u + kf_off;
        float s[8][4];
        #pragma unroll
        for (int ni = 0; ni < 8; ni++)
            #pragma unroll
            for (int j = 0; j < 4; j++) s[ni][j] = 0.f;
        #pragma unroll
        for (int kk = 0; kk < 4; kk++) {
            #pragma unroll
            for (int p = 0; p < 4; p++) {
                uint32_t b0, b1, b2, b3;
                LDSM4(b0, b1, b2, b3, Kb + (uint32_t)(p * 16 * 72 + kk * 16) * 2u);
                mma16(s[2*p],   qf[kk], b0, b1);
                mma16(s[2*p+1], qf[kk], b2, b3);
            }
        }

        // ---- online softmax (half 0: row g; half 1: row g+8)
        #pragma unroll
        for (int half_ = 0; half_ < 2; half_++) {
            float mx = -1e30f;
            #pragma unroll
            for (int ni = 0; ni < 8; ni++) {
                mx = fmaxf(mx, s[ni][half_ * 2 + 0]);
                mx = fmaxf(mx, s[ni][half_ * 2 + 1]);
            }
            mx = fmaxf(mx, __shfl_xor_sync(0xffffffffu, mx, 1));
            mx = fmaxf(mx, __shfl_xor_sync(0xffffffffu, mx, 2));
            float mnew = fmaxf(mrun[half_], mx);
            float sum = 0.f;
            #pragma unroll
            for (int ni = 0; ni < 8; ni++) {
                float p0 = exp2f((s[ni][half_ * 2 + 0] - mnew) * L2E);
                float p1 = exp2f((s[ni][half_ * 2 + 1] - mnew) * L2E);
                s[ni][half_ * 2 + 0] = p0;
                s[ni][half_ * 2 + 1] = p1;
                sum += p0 + p1;
            }
            sum += __shfl_xor_sync(0xffffffffu, sum, 1);
            sum += __shfl_xor_sync(0xffffffffu, sum, 2);
            if (mnew > mrun[half_]) {
                float alpha = exp2f((mrun[half_] - mnew) * L2E);
                lrun[half_] = lrun[half_] * alpha + sum;
                mrun[half_] = mnew;
                #pragma unroll
                for (int ni = 0; ni < 16; ni++) {
                    o[ni][half_ * 2 + 0] *= alpha;
                    o[ni][half_ * 2 + 1] *= alpha;
                }
            } else {
                lrun[half_] += sum;
            }
        }

        // ---- O += P V (shared V; P packs straight into A-fragment)
        uint32_t Vb = vbase + (uint32_t)(buf * 128 * 72) * 2u + kf_off;
        #pragma unroll
        for (int j = 0; j < 4; j++) {
            uint32_t a[4];
            a[0] = packh2(s[2*j][0],   s[2*j][1]);
            a[1] = packh2(s[2*j][2],   s[2*j][3]);
            a[2] = packh2(s[2*j+1][0], s[2*j+1][1]);
            a[3] = packh2(s[2*j+1][2], s[2*j+1][3]);
            #pragma unroll
            for (int vp = 0; vp < 8; vp++) {
                uint32_t b0, b1, b2, b3;
                LDSM4(b0, b1, b2, b3, Vb + (uint32_t)(vp * 16 * 72 + j * 16) * 2u);
                mma16(o[2*vp],   a, b0, b1);
                mma16(o[2*vp+1], a, b2, b3);
            }
        }
        __syncthreads();
    }

    // ---- fused combine epilogue (K/V smem dead -> reuse as f32 stage) ------
    if (hs == 1) {                       // head 2e+1: stage normalized o1
        #pragma unroll
        for (int half_ = 0; half_ < 2; half_++) {
            float inv = 1.f / lrun[half_];
            int r = w4 * 16 + g + half_ * 8;
            #pragma unroll
            for (int ni = 0; ni < 16; ni++) {
                *(float2*)(Os + r * 132 + ni * 8 + tg * 2) =
                    make_float2(o[ni][half_ * 2 + 0] * inv,
                                o[ni][half_ * 2 + 1] * inv);
            }
        }
    }
    __syncthreads();
    if (hs == 0) {                       // head 2e: diff + RMSNorm + store
        float lam = g_lambda;
        #pragma unroll
        for (int half_ = 0; half_ < 2; half_++) {
            float inv = 1.f / lrun[half_];
            int r = w4 * 16 + g + half_ * 8;
            float ss = 0.f;
            #pragma unroll
            for (int ni = 0; ni < 16; ni++) {
                float2 o1v = *(const float2*)(Os + r * 132 + ni * 8 + tg * 2);
                float x0 = o[ni][half_ * 2 + 0] * inv - lam * o1v.x;
                float x1 = o[ni][half_ * 2 + 1] * inv - lam * o1v.y;
                o[ni][half_ * 2 + 0] = x0;
                o[ni][half_ * 2 + 1] = x1;
                ss += x0 * x0 + x1 * x1;
            }
            ss += __shfl_xor_sync(0xffffffffu, ss, 1);
            ss += __shfl_xor_sync(0xffffffffu, ss, 2);
            float rms = rsqrtf(ss * (1.0f / HD2) + 1e-5f);
            int n = qt * 64 + r;
            __half* dst = g_combh + ((size_t)(b_ * NSEQ + n)) * DIMC + e * HD2;
            #pragma unroll
            for (int ni = 0; ni < 16; ni++) {
                int col = ni * 8 + tg * 2;
                float2 w2 = *(const float2*)(norm_w + col);
                *(uint32_t*)(dst + col) =
                    packh2(o[ni][half_ * 2 + 0] * rms * w2.x * 0.2f,
                           o[ni][half_ * 2 + 1] * rms * w2.y * 0.2f);
            }
        }
    }
}

// ---------------- launch -----------------------------------------------------
extern "C" void kernel_launch(void* const* d_in, const int* in_sizes, int n_in,
                              void* d_out, int out_size)
{
    const float* x      = (const float*)d_in[0];
    const float* Wq     = (const float*)d_in[1];
    const float* bq     = (const float*)d_in[2];
    const float* Wk     = (const float*)d_in[3];
    const float* bk     = (const float*)d_in[4];
    const float* Wv     = (const float*)d_in[5];
    const float* bv     = (const float*)d_in[6];
    const float* Wo     = (const float*)d_in[7];
    const float* bo     = (const float*)d_in[8];
    const float* norm_w = (const float*)d_in[9];
    const float* lq1    = (const float*)d_in[10];
    const float* lk1    = (const float*)d_in[11];
    const float* lq2    = (const float*)d_in[12];
    const float* lk2    = (const float*)d_in[13];
    float* out = (float*)d_out;

    lambda_kernel<<<1, 32>>>(lq1, lk1, lq2, lk2);

    __half* xh = nullptr; cudaGetSymbolAddress((void**)&xh, g_xh);
    __half* wh = nullptr; cudaGetSymbolAddress((void**)&wh, g_wh);
    round_kernel<<<MTOT * DIMC / 1024, 256>>>(x, xh);
    round4_kernel<<<4 * DIMC * DIMC / 1024, 256>>>(Wq, Wk, Wv, Wo);

    int gemm_smem = 4 * 2 * SSH * (int)sizeof(__half);   // 81,920 B
    cudaFuncSetAttribute(gemm_mma_kernel, cudaFuncAttributeMaxDynamicSharedMemorySize, gemm_smem);

    // fused Q/K/V projections: blockIdx.z selects mode
    gemm_mma_kernel<<<dim3(DIMC / 128, MTOT / 128, 3), 256, gemm_smem>>>(
        xh, nullptr, bq, bk, bv, nullptr, 1);

    vtrans_kernel<<<dim3(NSEQ / 64, NB * NEFF), 256>>>();

    // flash: 64-row q tiles, 256 threads, 2 CTAs/SM
    int flash_smem = (2 * 64 * 72 + 2 * 2 * 64 * 72 + 2 * 128 * 72) * (int)sizeof(__half); // 92,160
    cudaFuncSetAttribute(flash_kernel, cudaFuncAttributeMaxDynamicSharedMemorySize, flash_smem);
    flash_kernel<<<dim3(NSEQ / 64, NB * NEFF), 256, flash_smem>>>(norm_w);

    // output GEMM
    gemm_mma_kernel<<<dim3(DIMC / 128, MTOT / 128, 1), 256, gemm_smem>>>(
        nullptr, wh + 3 * DIMC * DIMC, bo, nullptr, nullptr, out, 0);
}